// round 8
// baseline (speedup 1.0000x reference)
#include <cuda_runtime.h>
#include <math.h>

#define Bsz 32
#define Rr  64
#define Ll  4096
#define Hh  768
#define KC  6          // K-chunks of 128
#define KCW 128        // chunk width

// Scratch (no device mallocs allowed)
__device__ float g_vp[KC][Bsz * Hh];  // partial v per K-chunk: [kc][b][h]
__device__ float g_t[Bsz * Ll];       // t[b,l] = hidden[b,l,:] . v[b,:]

// ---------------------------------------------------------------------------
// Kernel 1: partial GEMV  g_vp[kc][b][h] = sum_{k in chunk kc} W[h,k]*ans[b,k]
// lane = b, warp = h-row; block = (8 h-rows) x one K-chunk.
// W chunk loads are warp-broadcast LDG.128 (1 wavefront each); ans staged in
// smem transposed+padded so each lane's LDS.128 is conflict-free.
// NO cross-lane reduction anywhere. grid = (H/8=96, KC=6) = 576 blocks.
// ---------------------------------------------------------------------------
__global__ void __launch_bounds__(256)
k_gemv(const float* __restrict__ W, const float* __restrict__ ans) {
    __shared__ float ans_s[Bsz][KCW + 4];   // pad 4 -> LDS.128 conflict-free

    const int kc   = blockIdx.y;
    const int warp = threadIdx.x >> 5;
    const int lane = threadIdx.x & 31;
    const int h    = blockIdx.x * 8 + warp;

    // Stage ans[:, kc*128 : kc*128+128] transposed into smem (coalesced reads).
    for (int idx = threadIdx.x; idx < Bsz * KCW; idx += 256) {
        const int b = idx >> 7;          // 0..31
        const int k = idx & (KCW - 1);   // 0..127
        ans_s[b][k] = ans[(size_t)b * Hh + kc * KCW + k];
    }
    __syncthreads();

    const float4* wrow = (const float4*)(W + (size_t)h * Hh + kc * KCW);
    const float4* arow = (const float4*)(&ans_s[lane][0]);

    float4 acc = make_float4(0.f, 0.f, 0.f, 0.f);
#pragma unroll
    for (int j = 0; j < KCW / 4; j++) {
        float4 w4 = __ldg(&wrow[j]);     // broadcast: all lanes same address
        float4 a4 = arow[j];             // conflict-free LDS.128
        acc.x += w4.x * a4.x;
        acc.y += w4.y * a4.y;
        acc.z += w4.z * a4.z;
        acc.w += w4.w * a4.w;
    }
    // lane b owns the complete chunk-dot for (h, b): no reduction needed.
    g_vp[kc][lane * Hh + h] = (acc.x + acc.y) + (acc.z + acc.w);
}

// ---------------------------------------------------------------------------
// Kernel 2: t[b,l] = hidden[b,l,:] . v[b,:]    — the 402 MB HBM stream.
// v[b] assembled in smem by summing the 6 L2-hot partials (no extra pass).
// One warp per token, 16 tokens/warp, 8 warps/block, 128 tokens/block.
// grid = (L/128, B) = 1024 blocks; launch_bounds(256,8) -> single wave.
// ---------------------------------------------------------------------------
__global__ void __launch_bounds__(256, 8)
k_dot(const float* __restrict__ hidden) {
    __shared__ float4 sv[Hh / 4];
    const int b = blockIdx.y;

    for (int i = threadIdx.x; i < Hh / 4; i += 256) {
        float4 s = make_float4(0.f, 0.f, 0.f, 0.f);
#pragma unroll
        for (int kc = 0; kc < KC; kc++) {
            float4 p = ((const float4*)(g_vp[kc] + b * Hh))[i];
            s.x += p.x; s.y += p.y; s.z += p.z; s.w += p.w;
        }
        sv[i] = s;
    }
    __syncthreads();

    const int warp = threadIdx.x >> 5;
    const int lane = threadIdx.x & 31;
    const int l0   = blockIdx.x * 128 + warp * 16;   // this warp's 16 tokens

    const float4* base = (const float4*)(hidden + ((size_t)b * Ll + l0) * Hh) + lane;

    for (int i = 0; i < 16; i++) {
        float acc = 0.f;
#pragma unroll
        for (int k = 0; k < 6; k++) {
            float4 x  = __ldcs(base + (size_t)i * (Hh / 4) + k * 32);
            float4 vv = sv[lane + k * 32];
            acc += x.x * vv.x + x.y * vv.y + x.z * vv.z + x.w * vv.w;
        }
#pragma unroll
        for (int o = 16; o; o >>= 1)
            acc += __shfl_down_sync(0xffffffffu, acc, o);
        if (lane == 0)
            g_t[b * Ll + l0 + i] = acc;
    }
}

// ---------------------------------------------------------------------------
// Kernel 3: span-mean over t, mask, bias, softmax per batch row.
// One block per b; 8 warps, warp per span (8 spans each); t is L2-hot.
// NOTE: rubric_mask is bool -> harness promotes to int32.
// ---------------------------------------------------------------------------
__global__ void k_score(const int* __restrict__ span,
                        const int* __restrict__ mask,
                        const float* __restrict__ bias,
                        float* __restrict__ out) {
    __shared__ float sc[Rr];
    const int b    = blockIdx.x;
    const int warp = threadIdx.x >> 5;
    const int lane = threadIdx.x & 31;

    for (int r = warp; r < Rr; r += 8) {
        float score;
        if (mask[b * Rr + r] == 0) {
            score = -INFINITY;
        } else {
            const int s = span[(b * Rr + r) * 2 + 0];
            const int e = span[(b * Rr + r) * 2 + 1];
            const float* t = g_t + b * Ll;
            float acc = 0.f;
            for (int idx = s + lane; idx < e; idx += 32)
                acc += t[idx];
#pragma unroll
            for (int o = 16; o; o >>= 1)
                acc += __shfl_down_sync(0xffffffffu, acc, o);
            int len = e - s; if (len < 1) len = 1;
            score = acc / (float)len + bias[0];
        }
        if (lane == 0) sc[r] = score;
    }
    __syncthreads();

    if (threadIdx.x < 32) {
        const int tid = threadIdx.x;
        float a0 = sc[tid], a1 = sc[tid + 32];
        float m = fmaxf(a0, a1);
#pragma unroll
        for (int o = 16; o; o >>= 1)
            m = fmaxf(m, __shfl_xor_sync(0xffffffffu, m, o));
        float e0 = expf(a0 - m);
        float e1 = expf(a1 - m);
        float ssum = e0 + e1;
#pragma unroll
        for (int o = 16; o; o >>= 1)
            ssum += __shfl_xor_sync(0xffffffffu, ssum, o);
        out[b * Rr + tid]      = e0 / ssum;
        out[b * Rr + tid + 32] = e1 / ssum;
    }
}

// ---------------------------------------------------------------------------
extern "C" void kernel_launch(void* const* d_in, const int* in_sizes, int n_in,
                              void* d_out, int out_size) {
    const float* ans    = (const float*)d_in[0];   // (32, 768) f32
    const float* hidden = (const float*)d_in[1];   // (32, 4096, 768) f32
    const int*   span   = (const int*)d_in[2];     // (32, 64, 2) i32
    const int*   mask   = (const int*)d_in[3];     // (32, 64) bool -> i32
    const float* W      = (const float*)d_in[4];   // (1, 768, 768) f32
    const float* bias   = (const float*)d_in[5];   // (1,) f32
    float*       out    = (float*)d_out;           // (32, 64) f32

    k_gemv <<< dim3(Hh / 8, KC), 256 >>> (W, ans);
    k_dot  <<< dim3(Ll / 128, Bsz), 256 >>> (hidden);
    k_score<<< Bsz, 256 >>> (span, mask, bias, out);
}

// round 10
// speedup vs baseline: 1.0151x; 1.0151x over previous
#include <cuda_runtime.h>
#include <math.h>

#define Bsz 32
#define Rr  64
#define Ll  4096
#define Hh  768

// Scratch (no device mallocs allowed)
__device__ float g_v[Bsz * Hh];   // v[b,h] = sum_k W[h,k] * ans[b,k]
__device__ float g_t[Bsz * Ll];   // t[b,l] = hidden[b,l,:] . v[b,:]

// ---------------------------------------------------------------------------
// Kernel 1: batched GEMV  v[b,h] = W[h,:] . ans[b,:]
// grid = (H/8, B/16) = (96, 2) = 192 blocks, 256 thr.
// Block stages 16 ans rows in smem ONCE (48 KB, coalesced). Warp per h-row:
// W fragment (6 x float4) held in registers, reused across 16 batches.
// Cuts ans L2 traffic from ~73 MB (R7) to ~9 MB; W read twice (4.8 MB).
// ---------------------------------------------------------------------------
__global__ void __launch_bounds__(256)
k_gemv(const float* __restrict__ W, const float* __restrict__ ans) {
    __shared__ float ans_s[16][Hh + 4];     // pad -> conflict-free LDS.128

    const int warp = threadIdx.x >> 5;
    const int lane = threadIdx.x & 31;
    const int h    = blockIdx.x * 8 + warp;
    const int b0   = blockIdx.y * 16;

    // Stage 16 ans rows (coalesced global reads).
    for (int idx = threadIdx.x; idx < 16 * (Hh / 4); idx += 256) {
        const int bb = idx / (Hh / 4);
        const int kk = idx % (Hh / 4);
        ((float4*)&ans_s[bb][0])[kk] =
            ((const float4*)(ans + (size_t)(b0 + bb) * Hh))[kk];
    }
    __syncthreads();

    // W fragment in registers, reused across all 16 batches.
    const float4* wrow = (const float4*)(W + (size_t)h * Hh) + lane;
    float4 w[6];
#pragma unroll
    for (int k = 0; k < 6; k++) w[k] = wrow[k * 32];

#pragma unroll
    for (int j = 0; j < 16; j++) {
        float acc = 0.f;
#pragma unroll
        for (int k = 0; k < 6; k++) {
            float4 a4 = *(const float4*)&ans_s[j][(lane + k * 32) * 4];
            acc += w[k].x * a4.x + w[k].y * a4.y + w[k].z * a4.z + w[k].w * a4.w;
        }
#pragma unroll
        for (int o = 16; o; o >>= 1)
            acc += __shfl_down_sync(0xffffffffu, acc, o);
        if (lane == 0)
            g_v[(b0 + j) * Hh + h] = acc;
    }
}

// ---------------------------------------------------------------------------
// Kernel 2: t[b,l] = hidden[b,l,:] . v[b,:]    — the 402 MB HBM stream.
// One warp per token, 16 tokens/warp, 8 warps/block, 128 tokens/block.
// grid = (L/128, B) = 1024 blocks; launch_bounds(256,8) -> single wave.
// __ldcs evict-first streaming loads.
// ---------------------------------------------------------------------------
__global__ void __launch_bounds__(256, 8)
k_dot(const float* __restrict__ hidden) {
    __shared__ float4 sv[Hh / 4];
    const int b = blockIdx.y;

    for (int i = threadIdx.x; i < Hh / 4; i += 256)
        sv[i] = ((const float4*)(g_v + b * Hh))[i];
    __syncthreads();

    const int warp = threadIdx.x >> 5;
    const int lane = threadIdx.x & 31;
    const int l0   = blockIdx.x * 128 + warp * 16;   // this warp's 16 tokens

    const float4* base = (const float4*)(hidden + ((size_t)b * Ll + l0) * Hh) + lane;

    for (int i = 0; i < 16; i++) {
        float acc = 0.f;
#pragma unroll
        for (int k = 0; k < 6; k++) {
            float4 x  = __ldcs(base + (size_t)i * (Hh / 4) + k * 32);
            float4 vv = sv[lane + k * 32];
            acc += x.x * vv.x + x.y * vv.y + x.z * vv.z + x.w * vv.w;
        }
#pragma unroll
        for (int o = 16; o; o >>= 1)
            acc += __shfl_down_sync(0xffffffffu, acc, o);
        if (lane == 0)
            g_t[b * Ll + l0 + i] = acc;
    }
}

// ---------------------------------------------------------------------------
// Kernel 3: span-mean over t, mask, bias, softmax per batch row.
// One block per b; 8 warps, warp per span (8 spans each); t is L2-hot.
// NOTE: rubric_mask is bool -> harness promotes to int32.
// ---------------------------------------------------------------------------
__global__ void k_score(const int* __restrict__ span,
                        const int* __restrict__ mask,
                        const float* __restrict__ bias,
                        float* __restrict__ out) {
    __shared__ float sc[Rr];
    const int b    = blockIdx.x;
    const int warp = threadIdx.x >> 5;
    const int lane = threadIdx.x & 31;

    for (int r = warp; r < Rr; r += 8) {
        float score;
        if (mask[b * Rr + r] == 0) {
            score = -INFINITY;
        } else {
            const int s = span[(b * Rr + r) * 2 + 0];
            const int e = span[(b * Rr + r) * 2 + 1];
            const float* t = g_t + b * Ll;
            float acc = 0.f;
            for (int idx = s + lane; idx < e; idx += 32)
                acc += t[idx];
#pragma unroll
            for (int o = 16; o; o >>= 1)
                acc += __shfl_down_sync(0xffffffffu, acc, o);
            int len = e - s; if (len < 1) len = 1;
            score = acc / (float)len + bias[0];
        }
        if (lane == 0) sc[r] = score;
    }
    __syncthreads();

    if (threadIdx.x < 32) {
        const int tid = threadIdx.x;
        float a0 = sc[tid], a1 = sc[tid + 32];
        float m = fmaxf(a0, a1);
#pragma unroll
        for (int o = 16; o; o >>= 1)
            m = fmaxf(m, __shfl_xor_sync(0xffffffffu, m, o));
        float e0 = expf(a0 - m);
        float e1 = expf(a1 - m);
        float ssum = e0 + e1;
#pragma unroll
        for (int o = 16; o; o >>= 1)
            ssum += __shfl_xor_sync(0xffffffffu, ssum, o);
        out[b * Rr + tid]      = e0 / ssum;
        out[b * Rr + tid + 32] = e1 / ssum;
    }
}

// ---------------------------------------------------------------------------
extern "C" void kernel_launch(void* const* d_in, const int* in_sizes, int n_in,
                              void* d_out, int out_size) {
    const float* ans    = (const float*)d_in[0];   // (32, 768) f32
    const float* hidden = (const float*)d_in[1];   // (32, 4096, 768) f32
    const int*   span   = (const int*)d_in[2];     // (32, 64, 2) i32
    const int*   mask   = (const int*)d_in[3];     // (32, 64) bool -> i32
    const float* W      = (const float*)d_in[4];   // (1, 768, 768) f32
    const float* bias   = (const float*)d_in[5];   // (1,) f32
    float*       out    = (float*)d_out;           // (32, 64) f32

    k_gemv <<< dim3(Hh / 8, Bsz / 16), 256 >>> (W, ans);
    k_dot  <<< dim3(Ll / 128, Bsz), 256 >>> (hidden);
    k_score<<< Bsz, 256 >>> (span, mask, bias, out);
}

// round 11
// speedup vs baseline: 1.0692x; 1.0533x over previous
#include <cuda_runtime.h>
#include <math.h>

#define Bsz 32
#define Rr  64
#define Ll  4096
#define Hh  768

// Scratch (no device mallocs allowed)
__device__ float g_v[Bsz * Hh];   // v[b,h] = sum_k W[h,k] * ans[b,k]
__device__ float g_t[Bsz * Ll];   // t[b,l] = hidden[b,l,:] . v[b,:]
__device__ float g_sink[4];       // keeps prefetch loads live (never written in practice)

// ---------------------------------------------------------------------------
// Kernel 1: batched GEMV  v[b,h] = W[h,:] . ans[b,:]   (R7 config — proven)
// One warp per h-row, serving 4 batches; W fragment held in registers and
// reused across the 4 batches. block=128 (4 warps), grid=(H/4, B/4)=1536.
// EPILOGUE: each thread issues 8 __ldcg float4 prefetch reads of hidden,
// covering the FIRST token of every k_dot warp's range (8 tokens per (j,b)
// tile x 1024 tiles = 24 MB into L2) — uses the DRAM bandwidth that sits
// idle while this latency-bound kernel drains.
// ---------------------------------------------------------------------------
__global__ void k_gemv(const float* __restrict__ W, const float* __restrict__ ans,
                       const float* __restrict__ hidden) {
    const int warp = threadIdx.x >> 5;
    const int lane = threadIdx.x & 31;
    const int h    = blockIdx.x * 4 + warp;
    const int b0   = blockIdx.y * 4;

    const float4* wrow = (const float4*)(W + (size_t)h * Hh);
    float4 w[6];
#pragma unroll
    for (int k = 0; k < 6; k++) w[k] = wrow[lane + k * 32];

#pragma unroll
    for (int j = 0; j < 4; j++) {
        const int b = b0 + j;
        const float4* arow = (const float4*)(ans + (size_t)b * Hh);
        float acc = 0.f;
#pragma unroll
        for (int k = 0; k < 6; k++) {
            float4 a4 = arow[lane + k * 32];
            acc += w[k].x * a4.x + w[k].y * a4.y + w[k].z * a4.z + w[k].w * a4.w;
        }
#pragma unroll
        for (int o = 16; o; o >>= 1)
            acc += __shfl_down_sync(0xffffffffu, acc, o);
        if (lane == 0)
            g_v[b * Hh + h] = acc;
    }

    // ---- L2 prefetch of k_dot's warp-start tokens (24 MB) -----------------
    // Index space: 8192 tokens (b in [0,32), j in [0,32), w in [0,8) ->
    // token l = j*128 + w*16) x 192 float4 each = 1,572,864 float4.
    // 1536 blocks x 128 thr = 196,608 threads -> 8 float4 per thread.
    {
        const int gtid = (blockIdx.y * gridDim.x + blockIdx.x) * 128 + threadIdx.x;
        float s = 0.f;
#pragma unroll
        for (int r = 0; r < 8; r++) {
            const int p   = gtid + r * 196608;        // [0, 1572864)
            const int tok = p / 192;                  // [0, 8192)
            const int off = p - tok * 192;            // [0, 192)
            const int b   = tok >> 8;                 // [0, 32)
            const int rem = tok & 255;
            const int j   = rem >> 3;                 // [0, 32)
            const int wv  = rem & 7;                  // [0, 8)
            const size_t l = (size_t)b * Ll + j * 128 + wv * 16;
            float4 x = __ldcg(((const float4*)hidden) + l * (Hh / 4) + off);
            s += x.x;
        }
        if (s == 123456789.0f)      // data-dependent: never true, keeps loads live
            g_sink[0] = s;
    }
}

// ---------------------------------------------------------------------------
// Kernel 2: t[b,l] = hidden[b,l,:] . v[b,:]    — the 402 MB HBM stream.
// One warp per token, 16 tokens/warp, 8 warps/block, 128 tokens/block.
// grid = (L/128, B) = 1024 blocks; launch_bounds(256,8) -> single wave.
// First token of each warp is L2-hot from the k_gemv prefetch.
// ---------------------------------------------------------------------------
__global__ void __launch_bounds__(256, 8)
k_dot(const float* __restrict__ hidden) {
    __shared__ float4 sv[Hh / 4];
    const int b = blockIdx.y;

    for (int i = threadIdx.x; i < Hh / 4; i += 256)
        sv[i] = ((const float4*)(g_v + b * Hh))[i];
    __syncthreads();

    const int warp = threadIdx.x >> 5;
    const int lane = threadIdx.x & 31;
    const int l0   = blockIdx.x * 128 + warp * 16;   // this warp's 16 tokens

    const float4* base = (const float4*)(hidden + ((size_t)b * Ll + l0) * Hh) + lane;

    for (int i = 0; i < 16; i++) {
        float acc = 0.f;
#pragma unroll
        for (int k = 0; k < 6; k++) {
            float4 x  = __ldcs(base + (size_t)i * (Hh / 4) + k * 32);
            float4 vv = sv[lane + k * 32];
            acc += x.x * vv.x + x.y * vv.y + x.z * vv.z + x.w * vv.w;
        }
#pragma unroll
        for (int o = 16; o; o >>= 1)
            acc += __shfl_down_sync(0xffffffffu, acc, o);
        if (lane == 0)
            g_t[b * Ll + l0 + i] = acc;
    }
}

// ---------------------------------------------------------------------------
// Kernel 3: span-mean over t, mask, bias, softmax per batch row.
// One block per b; 8 warps, warp per span (8 spans each); t is L2-hot.
// NOTE: rubric_mask is bool -> harness promotes to int32.
// ---------------------------------------------------------------------------
__global__ void k_score(const int* __restrict__ span,
                        const int* __restrict__ mask,
                        const float* __restrict__ bias,
                        float* __restrict__ out) {
    __shared__ float sc[Rr];
    const int b    = blockIdx.x;
    const int warp = threadIdx.x >> 5;
    const int lane = threadIdx.x & 31;

    for (int r = warp; r < Rr; r += 8) {
        float score;
        if (mask[b * Rr + r] == 0) {
            score = -INFINITY;
        } else {
            const int s = span[(b * Rr + r) * 2 + 0];
            const int e = span[(b * Rr + r) * 2 + 1];
            const float* t = g_t + b * Ll;
            float acc = 0.f;
            for (int idx = s + lane; idx < e; idx += 32)
                acc += t[idx];
#pragma unroll
            for (int o = 16; o; o >>= 1)
                acc += __shfl_down_sync(0xffffffffu, acc, o);
            int len = e - s; if (len < 1) len = 1;
            score = acc / (float)len + bias[0];
        }
        if (lane == 0) sc[r] = score;
    }
    __syncthreads();

    if (threadIdx.x < 32) {
        const int tid = threadIdx.x;
        float a0 = sc[tid], a1 = sc[tid + 32];
        float m = fmaxf(a0, a1);
#pragma unroll
        for (int o = 16; o; o >>= 1)
            m = fmaxf(m, __shfl_xor_sync(0xffffffffu, m, o));
        float e0 = expf(a0 - m);
        float e1 = expf(a1 - m);
        float ssum = e0 + e1;
#pragma unroll
        for (int o = 16; o; o >>= 1)
            ssum += __shfl_xor_sync(0xffffffffu, ssum, o);
        out[b * Rr + tid]      = e0 / ssum;
        out[b * Rr + tid + 32] = e1 / ssum;
    }
}

// ---------------------------------------------------------------------------
extern "C" void kernel_launch(void* const* d_in, const int* in_sizes, int n_in,
                              void* d_out, int out_size) {
    const float* ans    = (const float*)d_in[0];   // (32, 768) f32
    const float* hidden = (const float*)d_in[1];   // (32, 4096, 768) f32
    const int*   span   = (const int*)d_in[2];     // (32, 64, 2) i32
    const int*   mask   = (const int*)d_in[3];     // (32, 64) bool -> i32
    const float* W      = (const float*)d_in[4];   // (1, 768, 768) f32
    const float* bias   = (const float*)d_in[5];   // (1,) f32
    float*       out    = (float*)d_out;           // (32, 64) f32

    k_gemv <<< dim3(Hh / 4, Bsz / 4), 128 >>> (W, ans, hidden);
    k_dot  <<< dim3(Ll / 128, Bsz), 256 >>> (hidden);
    k_score<<< Bsz, 256 >>> (span, mask, bias, out);
}

// round 12
// speedup vs baseline: 1.0697x; 1.0004x over previous
#include <cuda_runtime.h>
#include <math.h>

#define Bsz 32
#define Rr  64
#define Ll  4096
#define Hh  768

// Scratch (no device mallocs allowed)
__device__ float g_v[Bsz * Hh];   // v[b,h] = sum_k W[h,k] * ans[b,k]
__device__ float g_t[Bsz * Ll];   // t[b,l] = hidden[b,l,:] . v[b,:]
__device__ float g_sink[4];       // keeps prefetch loads live (never written in practice)

// ---------------------------------------------------------------------------
// Kernel 1: batched GEMV  v[b,h] = W[h,:] . ans[b,:]   (R7 config — proven)
// One warp per h-row, serving 4 batches; W fragment in registers reused
// across batches. block=128, grid=(H/4, B/4)=1536.
// PREFETCH (issued FIRST, consumed LAST): 4 scalar __ldcg loads per thread
// at 32B sector stride, covering the first token of every k_dot warp's
// range (8192 tokens x 3 KB = 24 MB into L2). Loads are independent of the
// GEMV, so their DRAM drain hides under the latency-bound GEMV body.
// ---------------------------------------------------------------------------
__global__ void k_gemv(const float* __restrict__ W, const float* __restrict__ ans,
                       const float* __restrict__ hidden) {
    // ---- Prefetch issue (sector-granular: 8192 tokens x 96 sectors) ------
    // p in [0, 786432): tok = p/96, sector = p%96; 196608 threads x 4.
    float pf[4];
    {
        const int gtid = (blockIdx.y * gridDim.x + blockIdx.x) * 128 + threadIdx.x;
#pragma unroll
        for (int r = 0; r < 4; r++) {
            const int p   = gtid + r * 196608;        // [0, 786432)
            const int tok = p / 96;                   // [0, 8192)
            const int sec = p - tok * 96;             // [0, 96)
            const int b   = tok >> 8;                 // [0, 32)
            const int rem = tok & 255;
            const int j   = rem >> 3;                 // [0, 32)
            const int wv  = rem & 7;                  // [0, 8)
            const size_t l = (size_t)b * Ll + j * 128 + wv * 16;
            pf[r] = __ldcg(hidden + l * Hh + sec * 8);
        }
    }

    // ---- GEMV body --------------------------------------------------------
    const int warp = threadIdx.x >> 5;
    const int lane = threadIdx.x & 31;
    const int h    = blockIdx.x * 4 + warp;
    const int b0   = blockIdx.y * 4;

    const float4* wrow = (const float4*)(W + (size_t)h * Hh);
    float4 w[6];
#pragma unroll
    for (int k = 0; k < 6; k++) w[k] = wrow[lane + k * 32];

#pragma unroll
    for (int j = 0; j < 4; j++) {
        const int b = b0 + j;
        const float4* arow = (const float4*)(ans + (size_t)b * Hh);
        float acc = 0.f;
#pragma unroll
        for (int k = 0; k < 6; k++) {
            float4 a4 = arow[lane + k * 32];
            acc += w[k].x * a4.x + w[k].y * a4.y + w[k].z * a4.z + w[k].w * a4.w;
        }
#pragma unroll
        for (int o = 16; o; o >>= 1)
            acc += __shfl_down_sync(0xffffffffu, acc, o);
        if (lane == 0)
            g_v[b * Hh + h] = acc;
    }

    // ---- Prefetch consume (data-dependent, never true) --------------------
    float s = (pf[0] + pf[1]) + (pf[2] + pf[3]);
    if (s == 123456789.0f)
        g_sink[0] = s;
}

// ---------------------------------------------------------------------------
// Kernel 2: t[b,l] = hidden[b,l,:] . v[b,:]    — the 402 MB HBM stream.
// One warp per token, 16 tokens/warp, 8 warps/block, 128 tokens/block.
// grid = (L/128, B) = 1024 blocks; launch_bounds(256,8) -> single wave.
// First token of each warp is L2-hot from the k_gemv prefetch.
// ---------------------------------------------------------------------------
__global__ void __launch_bounds__(256, 8)
k_dot(const float* __restrict__ hidden) {
    __shared__ float4 sv[Hh / 4];
    const int b = blockIdx.y;

    for (int i = threadIdx.x; i < Hh / 4; i += 256)
        sv[i] = ((const float4*)(g_v + b * Hh))[i];
    __syncthreads();

    const int warp = threadIdx.x >> 5;
    const int lane = threadIdx.x & 31;
    const int l0   = blockIdx.x * 128 + warp * 16;   // this warp's 16 tokens

    const float4* base = (const float4*)(hidden + ((size_t)b * Ll + l0) * Hh) + lane;

    for (int i = 0; i < 16; i++) {
        float acc = 0.f;
#pragma unroll
        for (int k = 0; k < 6; k++) {
            float4 x  = __ldcs(base + (size_t)i * (Hh / 4) + k * 32);
            float4 vv = sv[lane + k * 32];
            acc += x.x * vv.x + x.y * vv.y + x.z * vv.z + x.w * vv.w;
        }
#pragma unroll
        for (int o = 16; o; o >>= 1)
            acc += __shfl_down_sync(0xffffffffu, acc, o);
        if (lane == 0)
            g_t[b * Ll + l0 + i] = acc;
    }
}

// ---------------------------------------------------------------------------
// Kernel 3: span-mean over t, mask, bias, softmax per batch row.
// One block per b; 8 warps, warp per span (8 spans each); t is L2-hot.
// NOTE: rubric_mask is bool -> harness promotes to int32.
// ---------------------------------------------------------------------------
__global__ void k_score(const int* __restrict__ span,
                        const int* __restrict__ mask,
                        const float* __restrict__ bias,
                        float* __restrict__ out) {
    __shared__ float sc[Rr];
    const int b    = blockIdx.x;
    const int warp = threadIdx.x >> 5;
    const int lane = threadIdx.x & 31;

    for (int r = warp; r < Rr; r += 8) {
        float score;
        if (mask[b * Rr + r] == 0) {
            score = -INFINITY;
        } else {
            const int s = span[(b * Rr + r) * 2 + 0];
            const int e = span[(b * Rr + r) * 2 + 1];
            const float* t = g_t + b * Ll;
            float acc = 0.f;
            for (int idx = s + lane; idx < e; idx += 32)
                acc += t[idx];
#pragma unroll
            for (int o = 16; o; o >>= 1)
                acc += __shfl_down_sync(0xffffffffu, acc, o);
            int len = e - s; if (len < 1) len = 1;
            score = acc / (float)len + bias[0];
        }
        if (lane == 0) sc[r] = score;
    }
    __syncthreads();

    if (threadIdx.x < 32) {
        const int tid = threadIdx.x;
        float a0 = sc[tid], a1 = sc[tid + 32];
        float m = fmaxf(a0, a1);
#pragma unroll
        for (int o = 16; o; o >>= 1)
            m = fmaxf(m, __shfl_xor_sync(0xffffffffu, m, o));
        float e0 = expf(a0 - m);
        float e1 = expf(a1 - m);
        float ssum = e0 + e1;
#pragma unroll
        for (int o = 16; o; o >>= 1)
            ssum += __shfl_xor_sync(0xffffffffu, ssum, o);
        out[b * Rr + tid]      = e0 / ssum;
        out[b * Rr + tid + 32] = e1 / ssum;
    }
}

// ---------------------------------------------------------------------------
extern "C" void kernel_launch(void* const* d_in, const int* in_sizes, int n_in,
                              void* d_out, int out_size) {
    const float* ans    = (const float*)d_in[0];   // (32, 768) f32
    const float* hidden = (const float*)d_in[1];   // (32, 4096, 768) f32
    const int*   span   = (const int*)d_in[2];     // (32, 64, 2) i32
    const int*   mask   = (const int*)d_in[3];     // (32, 64) bool -> i32
    const float* W      = (const float*)d_in[4];   // (1, 768, 768) f32
    const float* bias   = (const float*)d_in[5];   // (1,) f32
    float*       out    = (float*)d_out;           // (32, 64) f32

    k_gemv <<< dim3(Hh / 4, Bsz / 4), 128 >>> (W, ans, hidden);
    k_dot  <<< dim3(Ll / 128, Bsz), 256 >>> (hidden);
    k_score<<< Bsz, 256 >>> (span, mask, bias, out);
}